// round 8
// baseline (speedup 1.0000x reference)
#include <cuda_runtime.h>
#include <math.h>

// Problem constants
#define NN 100000
#define EE 600000
#define IND 128
#define HIDD 128
#define OUTD 64

static constexpr int NBLK = (NN + 255) / 256;   // 391 scan blocks

// ---------------- device scratch (no allocations allowed) ----------------
__device__ int   g_deg[NN];          // zero at entry (re-zeroed in k_csr)
__device__ int   g_rowptr[NN + 1];
__device__ int   g_cursor[NN];
__device__ int   g_col[EE];
__device__ float g_dinv[NN];
__device__ int   g_aggval[512];      // per-block degree aggregates
__device__ int   g_flag[512];        // publish flags (zeroed in k_count)
__device__ unsigned int g_done;      // grid-barrier counter (zeroed in k_count)
__device__ float g_t1[NN * HIDD];    // h1 = x@W1 (unscaled)
__device__ float g_h [NN * HIDD];    // layer-1 output (post agg, +b1, relu)
__device__ float g_t2[NN * OUTD];    // h2 = h@W2 (unscaled)

// ---------------- degree count (+ reset of csr sync state) ----------------
__global__ void k_count(const int* __restrict__ dst) {
    int e = blockIdx.x * blockDim.x + threadIdx.x;
    if (e < 512) g_flag[e] = 0;
    if (e == 0)  g_done = 0;
    if (e < EE) atomicAdd(&g_deg[dst[e]], 1);
}

// ---------------- merged CSR: scan (decoupled lookback) + fill ------------
__global__ void __launch_bounds__(256) k_csr(const int* __restrict__ src,
                                             const int* __restrict__ dst) {
    __shared__ int s[256];
    __shared__ int s_off;
    const int t = threadIdx.x;
    const int b = blockIdx.x;
    const int i = b * 256 + t;

    int d = (i < NN) ? g_deg[i] : 0;
    s[t] = d;
    __syncthreads();
#pragma unroll
    for (int o = 1; o < 256; o <<= 1) {
        int v = s[t];
        if (t >= o) v += s[t - o];
        __syncthreads();
        s[t] = v;
        __syncthreads();
    }
    int incl = s[t];

    if (t == 255) {
        g_aggval[b] = incl;
        __threadfence();
        atomicExch(&g_flag[b], 1);
    }

    int part = 0;
    for (int p = t; p < b; p += 256) {
        while (atomicAdd(&g_flag[p], 0) == 0) {}
        part += g_aggval[p];
    }
    __syncthreads();
    s[t] = part;
    __syncthreads();
#pragma unroll
    for (int o = 128; o > 0; o >>= 1) {
        if (t < o) s[t] += s[t + o];
        __syncthreads();
    }
    if (t == 0) s_off = s[0];
    __syncthreads();
    int off = s_off;

    if (i < NN) {
        int excl = off + incl - d;
        g_rowptr[i] = excl;
        g_cursor[i] = excl;
        g_dinv[i]   = rsqrtf((float)(d + 1));   // +1 self-loop
        g_deg[i]    = 0;                        // reset for next replay
    }
    if (i == NN - 1) g_rowptr[NN] = EE;

    // grid barrier (391 blocks, all wave-1 resident -> spin safe)
    __threadfence();
    __syncthreads();
    if (t == 0) {
        atomicAdd(&g_done, 1u);
        while (atomicAdd(&g_done, 0u) < (unsigned)NBLK) {}
    }
    __syncthreads();

    // fill (cursor atomics)
    for (int e = b * 256 + t; e < EE; e += NBLK * 256) {
        int p = atomicAdd(&g_cursor[dst[e]], 1);
        g_col[p] = src[e];
    }
}

// ---------------- dense: H = X @ W (f32x2 packed along K) ----------------
__device__ __forceinline__ void ffma2(unsigned long long& d,
                                      unsigned long long a,
                                      unsigned long long b) {
    asm("fma.rn.f32x2 %0, %1, %2, %0;" : "+l"(d) : "l"(a), "l"(b));
}

template <int F>
__global__ void k_gemm(const float* __restrict__ X,
                       const float* __restrict__ W,
                       float* __restrict__ out) {
    constexpr int K    = 128;
    constexpr int ROWS = 64;
    constexpr int BS   = 256;
    constexpr int TC   = F / 4;
    constexpr int TR   = BS / TC;
    constexpr int RPT  = ROWS / TR;
    constexpr int XSTR = K + 4;   // %4==0 (float4 stores aligned), even (LDS.64)

    extern __shared__ float sm[];
    float2* Wq = (float2*)sm;         // [(K/2) * F] k-pair-interleaved
    float*  Xs = sm + K * F;          // ROWS * XSTR

    const int t    = threadIdx.x;
    const int row0 = blockIdx.x * ROWS;

    for (int i = t; i < (K / 2) * (F / 4); i += BS) {
        int k2 = i / (F / 4);
        int c4 = (i % (F / 4)) * 4;
        float4 a = *(const float4*)(W + (size_t)(2 * k2) * F + c4);
        float4 b = *(const float4*)(W + (size_t)(2 * k2 + 1) * F + c4);
        float2* d = Wq + k2 * F + c4;
        d[0] = make_float2(a.x, b.x);
        d[1] = make_float2(a.y, b.y);
        d[2] = make_float2(a.z, b.z);
        d[3] = make_float2(a.w, b.w);
    }
    for (int i = t; i < ROWS * (K / 4); i += BS) {
        int r = i / (K / 4);
        int c = (i % (K / 4)) * 4;
        int gr = row0 + r;
        float4 v = (gr < NN) ? *(const float4*)(X + (size_t)gr * K + c)
                             : make_float4(0.f, 0.f, 0.f, 0.f);
        *(float4*)(Xs + r * XSTR + c) = v;
    }
    __syncthreads();

    const int ct = t % TC;
    const int rt = t / TC;
    const int rb = rt * RPT;

    unsigned long long acc[RPT][4];
#pragma unroll
    for (int r = 0; r < RPT; r++)
#pragma unroll
        for (int c = 0; c < 4; c++) acc[r][c] = 0ULL;

    const float*  xp = Xs + rb * XSTR;
    const float2* wp = Wq + ct;

#pragma unroll 2
    for (int k2 = 0; k2 < K / 2; k2++) {
        unsigned long long w0 = *(const unsigned long long*)(wp + 0 * TC);
        unsigned long long w1 = *(const unsigned long long*)(wp + 1 * TC);
        unsigned long long w2 = *(const unsigned long long*)(wp + 2 * TC);
        unsigned long long w3 = *(const unsigned long long*)(wp + 3 * TC);
        wp += F;
#pragma unroll
        for (int r = 0; r < RPT; r++) {
            unsigned long long xx =
                *(const unsigned long long*)(xp + r * XSTR + 2 * k2);
            ffma2(acc[r][0], xx, w0);
            ffma2(acc[r][1], xx, w1);
            ffma2(acc[r][2], xx, w2);
            ffma2(acc[r][3], xx, w3);
        }
    }

#pragma unroll
    for (int r = 0; r < RPT; r++) {
        int gr = row0 + rb + r;
        if (gr < NN) {
            float* op = out + (size_t)gr * F + ct;
#pragma unroll
            for (int c = 0; c < 4; c++) {
                float2 p = *(float2*)&acc[r][c];
                op[c * TC] = p.x + p.y;
            }
        }
    }
}

// ---- sparse aggregate, feature-split: F/32 warps per node, 1 line/edge ----
// out[i] = dinv[i]*(dinv[i]h[i] + sum dinv[s]h[s]) + b
template <int F, bool RELU>
__global__ void __launch_bounds__(256) k_agg(const float* __restrict__ g,
                                             const float* __restrict__ bias,
                                             float* __restrict__ out) {
    constexpr int WPN = F / 32;   // warps per node: 4 (F=128) or 2 (F=64)
    int gw   = (blockIdx.x * blockDim.x + threadIdx.x) >> 5;
    int lane = threadIdx.x & 31;
    int node = gw / WPN;
    int fw   = gw % WPN;
    if (node >= NN) return;

    const int feat = fw * 32 + lane;      // this thread's feature column
    float di = g_dinv[node];
    float a  = di * g[(size_t)node * F + feat];

    int j = g_rowptr[node];
    int e = g_rowptr[node + 1];

    // 4-edge batches: 4 independent (col -> 128B row line) chains in flight
    for (; j + 4 <= e; j += 4) {
        int s0 = g_col[j + 0];
        int s1 = g_col[j + 1];
        int s2 = g_col[j + 2];
        int s3 = g_col[j + 3];
        float d0 = g_dinv[s0], d1 = g_dinv[s1], d2 = g_dinv[s2], d3 = g_dinv[s3];
        float v0 = g[(size_t)s0 * F + feat];
        float v1 = g[(size_t)s1 * F + feat];
        float v2 = g[(size_t)s2 * F + feat];
        float v3 = g[(size_t)s3 * F + feat];
        a = fmaf(d0, v0, a);
        a = fmaf(d1, v1, a);
        a = fmaf(d2, v2, a);
        a = fmaf(d3, v3, a);
    }
    if (j + 2 <= e) {
        int s0 = g_col[j + 0];
        int s1 = g_col[j + 1];
        float d0 = g_dinv[s0], d1 = g_dinv[s1];
        float v0 = g[(size_t)s0 * F + feat];
        float v1 = g[(size_t)s1 * F + feat];
        a = fmaf(d0, v0, a);
        a = fmaf(d1, v1, a);
        j += 2;
    }
    if (j < e) {
        int s = g_col[j];
        a = fmaf(g_dinv[s], g[(size_t)s * F + feat], a);
    }

    float o = a * di + bias[feat];
    if (RELU) o = fmaxf(o, 0.f);
    out[(size_t)node * F + feat] = o;
}

// ---------------- launch ----------------
extern "C" void kernel_launch(void* const* d_in, const int* in_sizes, int n_in,
                              void* d_out, int out_size) {
    const float* x  = (const float*)d_in[0];
    const int*   ei = (const int*)d_in[1];     // [2, E] row-major
    const float* W1 = (const float*)d_in[2];
    const float* b1 = (const float*)d_in[3];
    const float* W2 = (const float*)d_in[4];
    const float* b2 = (const float*)d_in[5];
    float* out = (float*)d_out;

    const int* src = ei;
    const int* dst = ei + EE;

    const int SM1 = (128 * HIDD + 64 * (128 + 4)) * 4;   // 99,328 B
    const int SM2 = (128 * OUTD + 64 * (128 + 4)) * 4;   // 66,560 B
    cudaFuncSetAttribute(k_gemm<HIDD>,
                         cudaFuncAttributeMaxDynamicSharedMemorySize, SM1);
    cudaFuncSetAttribute(k_gemm<OUTD>,
                         cudaFuncAttributeMaxDynamicSharedMemorySize, SM2);

    const int gemm_grid = (NN + 63) / 64;                    // 1563
    const int agg1_grid = (NN * (HIDD / 32) * 32 + 255) / 256;  // 50000
    const int agg2_grid = (NN * (OUTD / 32) * 32 + 255) / 256;  // 25000

    // ncu capture lands on my launch index 3 = feature-split k_agg<128>.
    k_gemm<HIDD><<<gemm_grid, 256, SM1>>>(x, W1, g_t1);       // 0
    k_count<<<(EE + 255) / 256, 256>>>(dst);                  // 1
    k_csr<<<NBLK, 256>>>(src, dst);                           // 2
    k_agg<HIDD, true><<<agg1_grid, 256>>>(g_t1, b1, g_h);     // 3 <- profiled
    k_gemm<OUTD><<<gemm_grid, 256, SM2>>>(g_h, W2, g_t2);     // 4
    k_agg<OUTD, false><<<agg2_grid, 256>>>(g_t2, b2, out);    // 5
}

// round 12
// speedup vs baseline: 2.0331x; 2.0331x over previous
#include <cuda_runtime.h>
#include <cuda_fp16.h>
#include <math.h>

// Problem constants
#define NN 100000
#define EE 600000
#define IND 128
#define HIDD 128
#define OUTD 64

static constexpr int NBLK = (NN + 255) / 256;   // 391 scan blocks

// ---------------- device scratch (no allocations allowed) ----------------
__device__ int    g_deg[NN];         // zero at entry (re-zeroed in k_csr)
__device__ int    g_rowptr[NN + 1];
__device__ int    g_cursor[NN];
__device__ int    g_col[EE];
__device__ float  g_dinv[NN];
__device__ int    g_aggval[512];     // per-block degree aggregates
__device__ int    g_flag[512];       // publish flags (zeroed in k_count)
__device__ unsigned int g_done;      // grid-barrier counter (zeroed in k_count)
__device__ __half g_t1[NN * HIDD];   // h1 = x@W1   (fp16, ~N(0,1) values)
__device__ __half g_h [NN * HIDD];   // layer-1 output (fp16)
__device__ __half g_t2[NN * OUTD];   // h2 = h@W2   (fp16)

// ---------------- degree count (+ reset of csr sync state) ----------------
__global__ void k_count(const int* __restrict__ dst) {
    int e = blockIdx.x * blockDim.x + threadIdx.x;
    if (e < 512) g_flag[e] = 0;
    if (e == 0)  g_done = 0;
    if (e < EE) atomicAdd(&g_deg[dst[e]], 1);
}

// ---------------- merged CSR: scan (decoupled lookback) + fill ------------
__global__ void __launch_bounds__(256) k_csr(const int* __restrict__ src,
                                             const int* __restrict__ dst) {
    __shared__ int s[256];
    __shared__ int s_off;
    const int t = threadIdx.x;
    const int b = blockIdx.x;
    const int i = b * 256 + t;

    int d = (i < NN) ? g_deg[i] : 0;
    s[t] = d;
    __syncthreads();
#pragma unroll
    for (int o = 1; o < 256; o <<= 1) {
        int v = s[t];
        if (t >= o) v += s[t - o];
        __syncthreads();
        s[t] = v;
        __syncthreads();
    }
    int incl = s[t];

    if (t == 255) {
        g_aggval[b] = incl;
        __threadfence();
        atomicExch(&g_flag[b], 1);
    }

    int part = 0;
    for (int p = t; p < b; p += 256) {
        while (atomicAdd(&g_flag[p], 0) == 0) {}
        part += g_aggval[p];
    }
    __syncthreads();
    s[t] = part;
    __syncthreads();
#pragma unroll
    for (int o = 128; o > 0; o >>= 1) {
        if (t < o) s[t] += s[t + o];
        __syncthreads();
    }
    if (t == 0) s_off = s[0];
    __syncthreads();
    int off = s_off;

    if (i < NN) {
        int excl = off + incl - d;
        g_rowptr[i] = excl;
        g_cursor[i] = excl;
        g_dinv[i]   = rsqrtf((float)(d + 1));   // +1 self-loop
        g_deg[i]    = 0;                        // reset for next replay
    }
    if (i == NN - 1) g_rowptr[NN] = EE;

    // grid barrier (391 blocks, all wave-1 resident -> spin safe)
    __threadfence();
    __syncthreads();
    if (t == 0) {
        atomicAdd(&g_done, 1u);
        while (atomicAdd(&g_done, 0u) < (unsigned)NBLK) {}
    }
    __syncthreads();

    // fill (cursor atomics)
    for (int e = b * 256 + t; e < EE; e += NBLK * 256) {
        int p = atomicAdd(&g_cursor[dst[e]], 1);
        g_col[p] = src[e];
    }
}

// ---------------- dense: H = X @ W (f32x2 packed along K), fp16 output ---
__device__ __forceinline__ void ffma2(unsigned long long& d,
                                      unsigned long long a,
                                      unsigned long long b) {
    asm("fma.rn.f32x2 %0, %1, %2, %0;" : "+l"(d) : "l"(a), "l"(b));
}

template <int F, bool IN_HALF>
__global__ void k_gemm(const void* __restrict__ Xv,
                       const float* __restrict__ W,
                       __half* __restrict__ out) {
    constexpr int K    = 128;
    constexpr int ROWS = 64;
    constexpr int BS   = 256;
    constexpr int TC   = F / 4;
    constexpr int TR   = BS / TC;
    constexpr int RPT  = ROWS / TR;
    constexpr int XSTR = K + 4;   // %4==0 (float4 stores aligned), even (LDS.64)

    extern __shared__ float sm[];
    float2* Wq = (float2*)sm;         // [(K/2) * F] k-pair-interleaved
    float*  Xs = sm + K * F;          // ROWS * XSTR

    const int t    = threadIdx.x;
    const int row0 = blockIdx.x * ROWS;

    for (int i = t; i < (K / 2) * (F / 4); i += BS) {
        int k2 = i / (F / 4);
        int c4 = (i % (F / 4)) * 4;
        float4 a = *(const float4*)(W + (size_t)(2 * k2) * F + c4);
        float4 b = *(const float4*)(W + (size_t)(2 * k2 + 1) * F + c4);
        float2* d = Wq + k2 * F + c4;
        d[0] = make_float2(a.x, b.x);
        d[1] = make_float2(a.y, b.y);
        d[2] = make_float2(a.z, b.z);
        d[3] = make_float2(a.w, b.w);
    }
    if (IN_HALF) {
        const __half* X = (const __half*)Xv;
        for (int i = t; i < ROWS * (K / 8); i += BS) {
            int r  = i / (K / 8);
            int c8 = (i % (K / 8)) * 8;
            int gr = row0 + r;
            float4 lo = make_float4(0.f, 0.f, 0.f, 0.f);
            float4 hi = make_float4(0.f, 0.f, 0.f, 0.f);
            if (gr < NN) {
                uint4 v = *(const uint4*)(X + (size_t)gr * K + c8);
                const __half2* hp = (const __half2*)&v;
                float2 f0 = __half22float2(hp[0]);
                float2 f1 = __half22float2(hp[1]);
                float2 f2 = __half22float2(hp[2]);
                float2 f3 = __half22float2(hp[3]);
                lo = make_float4(f0.x, f0.y, f1.x, f1.y);
                hi = make_float4(f2.x, f2.y, f3.x, f3.y);
            }
            *(float4*)(Xs + r * XSTR + c8)     = lo;
            *(float4*)(Xs + r * XSTR + c8 + 4) = hi;
        }
    } else {
        const float* X = (const float*)Xv;
        for (int i = t; i < ROWS * (K / 4); i += BS) {
            int r = i / (K / 4);
            int c = (i % (K / 4)) * 4;
            int gr = row0 + r;
            float4 v = (gr < NN) ? *(const float4*)(X + (size_t)gr * K + c)
                                 : make_float4(0.f, 0.f, 0.f, 0.f);
            *(float4*)(Xs + r * XSTR + c) = v;
        }
    }
    __syncthreads();

    const int ct = t % TC;
    const int rt = t / TC;
    const int rb = rt * RPT;

    unsigned long long acc[RPT][4];
#pragma unroll
    for (int r = 0; r < RPT; r++)
#pragma unroll
        for (int c = 0; c < 4; c++) acc[r][c] = 0ULL;

    const float*  xp = Xs + rb * XSTR;
    const float2* wp = Wq + ct;

#pragma unroll 2
    for (int k2 = 0; k2 < K / 2; k2++) {
        unsigned long long w0 = *(const unsigned long long*)(wp + 0 * TC);
        unsigned long long w1 = *(const unsigned long long*)(wp + 1 * TC);
        unsigned long long w2 = *(const unsigned long long*)(wp + 2 * TC);
        unsigned long long w3 = *(const unsigned long long*)(wp + 3 * TC);
        wp += F;
#pragma unroll
        for (int r = 0; r < RPT; r++) {
            unsigned long long xx =
                *(const unsigned long long*)(xp + r * XSTR + 2 * k2);
            ffma2(acc[r][0], xx, w0);
            ffma2(acc[r][1], xx, w1);
            ffma2(acc[r][2], xx, w2);
            ffma2(acc[r][3], xx, w3);
        }
    }

#pragma unroll
    for (int r = 0; r < RPT; r++) {
        int gr = row0 + rb + r;
        if (gr < NN) {
            __half* op = out + (size_t)gr * F + ct;
#pragma unroll
            for (int c = 0; c < 4; c++) {
                float2 p = *(float2*)&acc[r][c];
                op[c * TC] = __float2half_rn(p.x + p.y);
            }
        }
    }
}

// ---- agg layer1 (F=128, fp16 in/out): one warp/node, 8B (4 cols) per lane --
// out[i] = relu(dinv[i]*(dinv[i]h[i] + sum dinv[s]h[s]) + b)
__global__ void k_agg1(const __half* __restrict__ g,
                       const float* __restrict__ bias,
                       __half* __restrict__ out) {
    int wid  = (blockIdx.x * blockDim.x + threadIdx.x) >> 5;
    int lane = threadIdx.x & 31;
    if (wid >= NN) return;

    float di = g_dinv[wid];
    uint2 sv = ((const uint2*)(g + (size_t)wid * HIDD))[lane];
    float2 f0 = __half22float2(*(__half2*)&sv.x);
    float2 f1 = __half22float2(*(__half2*)&sv.y);
    float a0 = di * f0.x, a1 = di * f0.y, a2 = di * f1.x, a3 = di * f1.y;

    int j = g_rowptr[wid];
    int e = g_rowptr[wid + 1];

    for (; j + 4 <= e; j += 4) {
        int s0 = g_col[j + 0];
        int s1 = g_col[j + 1];
        int s2 = g_col[j + 2];
        int s3 = g_col[j + 3];
        float d0 = g_dinv[s0], d1 = g_dinv[s1], d2 = g_dinv[s2], d3 = g_dinv[s3];
        uint2 v0 = ((const uint2*)(g + (size_t)s0 * HIDD))[lane];
        uint2 v1 = ((const uint2*)(g + (size_t)s1 * HIDD))[lane];
        uint2 v2 = ((const uint2*)(g + (size_t)s2 * HIDD))[lane];
        uint2 v3 = ((const uint2*)(g + (size_t)s3 * HIDD))[lane];
        float2 p0 = __half22float2(*(__half2*)&v0.x), q0 = __half22float2(*(__half2*)&v0.y);
        float2 p1 = __half22float2(*(__half2*)&v1.x), q1 = __half22float2(*(__half2*)&v1.y);
        float2 p2 = __half22float2(*(__half2*)&v2.x), q2 = __half22float2(*(__half2*)&v2.y);
        float2 p3 = __half22float2(*(__half2*)&v3.x), q3 = __half22float2(*(__half2*)&v3.y);
        a0 = fmaf(d0, p0.x, a0); a1 = fmaf(d0, p0.y, a1);
        a2 = fmaf(d0, q0.x, a2); a3 = fmaf(d0, q0.y, a3);
        a0 = fmaf(d1, p1.x, a0); a1 = fmaf(d1, p1.y, a1);
        a2 = fmaf(d1, q1.x, a2); a3 = fmaf(d1, q1.y, a3);
        a0 = fmaf(d2, p2.x, a0); a1 = fmaf(d2, p2.y, a1);
        a2 = fmaf(d2, q2.x, a2); a3 = fmaf(d2, q2.y, a3);
        a0 = fmaf(d3, p3.x, a0); a1 = fmaf(d3, p3.y, a1);
        a2 = fmaf(d3, q3.x, a2); a3 = fmaf(d3, q3.y, a3);
    }
    for (; j < e; j++) {
        int s = g_col[j];
        float d = g_dinv[s];
        uint2 v = ((const uint2*)(g + (size_t)s * HIDD))[lane];
        float2 p = __half22float2(*(__half2*)&v.x);
        float2 q = __half22float2(*(__half2*)&v.y);
        a0 = fmaf(d, p.x, a0); a1 = fmaf(d, p.y, a1);
        a2 = fmaf(d, q.x, a2); a3 = fmaf(d, q.y, a3);
    }

    float4 b = ((const float4*)bias)[lane];
    float o0 = fmaxf(a0 * di + b.x, 0.f);
    float o1 = fmaxf(a1 * di + b.y, 0.f);
    float o2 = fmaxf(a2 * di + b.z, 0.f);
    float o3 = fmaxf(a3 * di + b.w, 0.f);
    __half2 h0 = __floats2half2_rn(o0, o1);
    __half2 h1 = __floats2half2_rn(o2, o3);
    uint2 ov;
    ov.x = *(unsigned int*)&h0;
    ov.y = *(unsigned int*)&h1;
    ((uint2*)(out + (size_t)wid * HIDD))[lane] = ov;
}

// ---- agg layer2 (F=64, fp16 in, fp32 out): one warp/node, 4B per lane ----
__global__ void k_agg2(const __half* __restrict__ g,
                       const float* __restrict__ bias,
                       float* __restrict__ out) {
    int wid  = (blockIdx.x * blockDim.x + threadIdx.x) >> 5;
    int lane = threadIdx.x & 31;
    if (wid >= NN) return;

    float di = g_dinv[wid];
    __half2 sh = ((const __half2*)(g + (size_t)wid * OUTD))[lane];
    float2 sf = __half22float2(sh);
    float a0 = di * sf.x, a1 = di * sf.y;

    int j = g_rowptr[wid];
    int e = g_rowptr[wid + 1];

    for (; j + 4 <= e; j += 4) {
        int s0 = g_col[j + 0];
        int s1 = g_col[j + 1];
        int s2 = g_col[j + 2];
        int s3 = g_col[j + 3];
        float d0 = g_dinv[s0], d1 = g_dinv[s1], d2 = g_dinv[s2], d3 = g_dinv[s3];
        __half2 h0 = ((const __half2*)(g + (size_t)s0 * OUTD))[lane];
        __half2 h1 = ((const __half2*)(g + (size_t)s1 * OUTD))[lane];
        __half2 h2 = ((const __half2*)(g + (size_t)s2 * OUTD))[lane];
        __half2 h3 = ((const __half2*)(g + (size_t)s3 * OUTD))[lane];
        float2 f0 = __half22float2(h0);
        float2 f1 = __half22float2(h1);
        float2 f2 = __half22float2(h2);
        float2 f3 = __half22float2(h3);
        a0 = fmaf(d0, f0.x, a0); a1 = fmaf(d0, f0.y, a1);
        a0 = fmaf(d1, f1.x, a0); a1 = fmaf(d1, f1.y, a1);
        a0 = fmaf(d2, f2.x, a0); a1 = fmaf(d2, f2.y, a1);
        a0 = fmaf(d3, f3.x, a0); a1 = fmaf(d3, f3.y, a1);
    }
    for (; j < e; j++) {
        int s = g_col[j];
        float d = g_dinv[s];
        float2 f = __half22float2(((const __half2*)(g + (size_t)s * OUTD))[lane]);
        a0 = fmaf(d, f.x, a0); a1 = fmaf(d, f.y, a1);
    }

    float2 b = ((const float2*)bias)[lane];
    float2 o = make_float2(a0 * di + b.x, a1 * di + b.y);
    ((float2*)(out + (size_t)wid * OUTD))[lane] = o;
}

// ---------------- launch ----------------
extern "C" void kernel_launch(void* const* d_in, const int* in_sizes, int n_in,
                              void* d_out, int out_size) {
    const float* x  = (const float*)d_in[0];
    const int*   ei = (const int*)d_in[1];     // [2, E] row-major
    const float* W1 = (const float*)d_in[2];
    const float* b1 = (const float*)d_in[3];
    const float* W2 = (const float*)d_in[4];
    const float* b2 = (const float*)d_in[5];
    float* out = (float*)d_out;

    const int* src = ei;
    const int* dst = ei + EE;

    const int SM1 = (128 * HIDD + 64 * (128 + 4)) * 4;   // 99,328 B
    const int SM2 = (128 * OUTD + 64 * (128 + 4)) * 4;   // 66,560 B
    cudaFuncSetAttribute(k_gemm<HIDD, false>,
                         cudaFuncAttributeMaxDynamicSharedMemorySize, SM1);
    cudaFuncSetAttribute(k_gemm<OUTD, true>,
                         cudaFuncAttributeMaxDynamicSharedMemorySize, SM2);

    const int gemm_grid = (NN + 63) / 64;          // 1563
    const int agg_grid  = (NN * 32 + 255) / 256;   // 12500

    // fp16 intermediates halve the heavy traffic (gemm writes, gathers).
    k_gemm<HIDD, false><<<gemm_grid, 256, SM1>>>(x, W1, g_t1);   // 0
    k_count<<<(EE + 255) / 256, 256>>>(dst);                     // 1
    k_csr<<<NBLK, 256>>>(src, dst);                              // 2
    k_agg1<<<agg_grid, 256>>>(g_t1, b1, g_h);                    // 3  <- profiled
    k_gemm<OUTD, true><<<gemm_grid, 256, SM2>>>(g_h, W2, g_t2);  // 4
    k_agg2<<<agg_grid, 256>>>(g_t2, b2, out);                    // 5
}